// round 13
// baseline (speedup 1.0000x reference)
#include <cuda_runtime.h>
#include <cuda_fp16.h>
#include <math.h>
#include <stdint.h>

#define BB 2
#define SS 2048
#define DD 1024
#define HH 16
#define DKK 64

// Q pre-scale: 1/sqrt(64) * log2(e)  (softmax runs in exp2 domain)
#define QSCALE 0.1803368801111204f
#define ONESH2 0x3C003C00u          // fp16x2 {1.0, 1.0}

// Scratch (allocation-free rule: __device__ globals)
__device__ __half g_Qh[BB*HH*SS*DKK];     // [b][h][s][dk] fp16, pre-scaled
__device__ __half g_Kh[BB*HH*SS*DKK];
__device__ __half g_Vh[BB*HH*SS*DKK];
__device__ __half g_attnh[BB*SS*DD];      // [b][s][h*64+dk] fp16
__device__ __half g_xq[BB*SS*DD];         // fp16 inputs
__device__ __half g_xk[BB*SS*DD];
__device__ __half g_xv[BB*SS*DD];
__device__ __half g_wh[4*DD*DD];          // fp16 W_q,W_k,W_v,W_o

__device__ __forceinline__ uint32_t smem_u32(const void* p) {
    uint32_t a;
    asm("{ .reg .u64 t; cvta.to.shared.u64 t, %1; cvt.u32.u64 %0, t; }"
        : "=r"(a) : "l"(p));
    return a;
}
__device__ __forceinline__ void cp16(uint32_t saddr, const void* g) {
    asm volatile("cp.async.cg.shared.global [%0], [%1], 16;"
                 :: "r"(saddr), "l"(g) : "memory");
}
__device__ __forceinline__ void cp_commit() {
    asm volatile("cp.async.commit_group;" ::: "memory");
}
template<int N> __device__ __forceinline__ void cp_wait() {
    asm volatile("cp.async.wait_group %0;" :: "n"(N) : "memory");
}
__device__ __forceinline__ void ldm4(uint32_t* r, uint32_t addr) {
    asm volatile("ldmatrix.sync.aligned.m8n8.x4.shared.b16 {%0,%1,%2,%3}, [%4];"
        : "=r"(r[0]), "=r"(r[1]), "=r"(r[2]), "=r"(r[3]) : "r"(addr));
}
__device__ __forceinline__ void ldm4t(uint32_t* r, uint32_t addr) {
    asm volatile("ldmatrix.sync.aligned.m8n8.x4.trans.shared.b16 {%0,%1,%2,%3}, [%4];"
        : "=r"(r[0]), "=r"(r[1]), "=r"(r[2]), "=r"(r[3]) : "r"(addr));
}
__device__ __forceinline__ void mma_f16(float* d, const uint32_t* a,
                                        uint32_t b0, uint32_t b1)
{
    asm volatile(
        "mma.sync.aligned.m16n8k16.row.col.f32.f16.f16.f32 "
        "{%0,%1,%2,%3}, {%4,%5,%6,%7}, {%8,%9}, {%0,%1,%2,%3};"
        : "+f"(d[0]), "+f"(d[1]), "+f"(d[2]), "+f"(d[3])
        : "r"(a[0]), "r"(a[1]), "r"(a[2]), "r"(a[3]), "r"(b0), "r"(b1));
}
__device__ __forceinline__ uint32_t h2pack(float x, float y) {
    __half2 h = __floats2half2_rn(x, y);
    return *reinterpret_cast<uint32_t*>(&h);
}
__device__ __forceinline__ uint32_t ex2h2(uint32_t x) {
    uint32_t r; asm("ex2.approx.f16x2 %0, %1;" : "=r"(r) : "r"(x)); return r;
}

// ===========================================================================
// Prepass: fp32 -> fp16 (RN), single launch (z selects tensor)
// ===========================================================================
__global__ void cvt_all(__half* xq, __half* xk, __half* xv, __half* wh,
                        const float* q, const float* k, const float* v,
                        const float* w0, const float* w1,
                        const float* w2, const float* w3,
                        int n4_in, int n4_w)
{
    const int z = blockIdx.z;
    const float* s;
    __half* d;
    int n4;
    if (z < 3) {
        s = z == 0 ? q : z == 1 ? k : v;
        d = z == 0 ? xq : z == 1 ? xk : xv;
        n4 = n4_in;
    } else {
        s = z == 3 ? w0 : z == 4 ? w1 : z == 5 ? w2 : w3;
        d = wh + (size_t)(z - 3) * (size_t)n4_w * 4;
        n4 = n4_w;
    }
    int i = blockIdx.x * blockDim.x + threadIdx.x;
    int str = gridDim.x * blockDim.x;
    for (; i < n4; i += str) {
        float4 vv = ((const float4*)s)[i];
        uint2 u;
        u.x = h2pack(vv.x, vv.y);
        u.y = h2pack(vv.z, vv.w);
        ((uint2*)d)[i] = u;
    }
}

// ===========================================================================
// fp16 GEMM (R13): SMEM-FREE. Fragments loaded directly with LDG.32
// (A-frag and B-frag are both k-contiguous 32-bit pairs — same pattern as
// attention's Q fragments, proven since R6). No cp.async, no ldmatrix,
// no barriers: kills the LDGSTS issue-rate bottleneck (8 cyc/op/SMSP)
// that bounded the staged version. L1 serves the 4x (A) / 2x (W) warp reuse.
// ===========================================================================
template<bool REORDER>
__device__ __forceinline__ void gemm_body(const __half* __restrict__ A,
                                          const __half* __restrict__ W,
                                          const float* __restrict__ bias,
                                          void* Cout, float oscale)
{
    const int tid = threadIdx.x;
    const int bm = blockIdx.y * 128;
    const int bn = blockIdx.x * 128;
    const int wid = tid >> 5, lane = tid & 31;
    const int warpM = wid >> 2, warpN = wid & 3;
    const int gg = lane >> 2, tt = lane & 3;

    float acc[16][4];
#pragma unroll
    for (int i = 0; i < 16; i++)
#pragma unroll
        for (int j = 0; j < 4; j++) acc[i][j] = 0.f;

    // per-lane fragment base pointers
    const __half* pa = A + (size_t)(bm + warpM * 64 + gg) * 1024 + 2 * tt;
    const __half* pw = W + (size_t)(bn + warpN * 32 + gg) * 1024 + 2 * tt;

#pragma unroll 2
    for (int c = 0; c < 32; c++) {
        uint32_t af[2][4][4], bf[2][4][2];
#pragma unroll
        for (int ks = 0; ks < 2; ks++) {
#pragma unroll
            for (int mt = 0; mt < 4; mt++) {
                const __half* p = pa + mt * 16 * 1024 + ks * 16;
                af[ks][mt][0] = *(const uint32_t*)(p);
                af[ks][mt][1] = *(const uint32_t*)(p + 8 * 1024);
                af[ks][mt][2] = *(const uint32_t*)(p + 8);
                af[ks][mt][3] = *(const uint32_t*)(p + 8 * 1024 + 8);
            }
#pragma unroll
            for (int nt = 0; nt < 4; nt++) {
                const __half* p = pw + nt * 8 * 1024 + ks * 16;
                bf[ks][nt][0] = *(const uint32_t*)(p);
                bf[ks][nt][1] = *(const uint32_t*)(p + 8);
            }
        }
#pragma unroll
        for (int ks = 0; ks < 2; ks++)
#pragma unroll
            for (int mt = 0; mt < 4; mt++)
#pragma unroll
                for (int nt = 0; nt < 4; nt++)
                    mma_f16(acc[mt*4+nt], af[ks][mt],
                            bf[ks][nt][0], bf[ks][nt][1]);
        pa += 32;
        pw += 32;
    }

#pragma unroll
    for (int mt = 0; mt < 4; mt++) {
#pragma unroll
        for (int nt = 0; nt < 4; nt++) {
            const int n0 = bn + warpN * 32 + nt * 8 + 2 * tt;
            const float2 bb = *(const float2*)(bias + n0);
#pragma unroll
            for (int half = 0; half < 2; half++) {
                const int m = bm + warpM * 64 + mt * 16 + gg + half * 8;
                float vx = (acc[mt*4+nt][half*2+0] + bb.x) * oscale;
                float vy = (acc[mt*4+nt][half*2+1] + bb.y) * oscale;
                if (REORDER) {
                    const int b = m >> 11, s = m & 2047;
                    const int h = n0 >> 6, dk = n0 & 63;
                    size_t idx = ((size_t)(b * HH + h) * SS + s) * DKK + dk;
                    *(uint32_t*)((__half*)Cout + idx) = h2pack(vx, vy);
                } else {
                    size_t idx = (size_t)m * DD + n0;
                    *(float2*)((float*)Cout + idx) = make_float2(vx, vy);
                }
            }
        }
    }
}

__global__ void __launch_bounds__(256, 2)
gemm_qkv(const __half* __restrict__ xq, const __half* __restrict__ xk,
         const __half* __restrict__ xv, const __half* __restrict__ w4,
         const float* bq, const float* bk, const float* bv,
         __half* oq, __half* ok, __half* ov)
{
    const int z = blockIdx.z;
    const __half* A = z == 0 ? xq : z == 1 ? xk : xv;
    const __half* W = w4 + (size_t)z * DD * DD;
    const float* bias = z == 0 ? bq : z == 1 ? bk : bv;
    __half* out = z == 0 ? oq : z == 1 ? ok : ov;
    gemm_body<true>(A, W, bias, out, z == 0 ? QSCALE : 1.0f);
}

__global__ void __launch_bounds__(256, 2)
gemm_out(const __half* __restrict__ A, const __half* __restrict__ W,
         const float* bias, float* C)
{
    gemm_body<false>(A, W, bias, C, 1.0f);
}

// ===========================================================================
// Flash attention (EXACT R12 — proven best): fp16 mma, causal, max-free
// exp2 softmax, split-half pipelining, ones-column l on the tensor pipe.
// ===========================================================================
#define KV_T 9216u        // bytes per tensor tile: 64 * 144
#define KV_S 18432u       // bytes per stage (K+V)
#define ATT_SMEM (2 * 18432)   // 36864 B

__global__ void __launch_bounds__(256, 2)
attn_h()
{
    extern __shared__ __half smh[];
    const uint32_t sbase = smem_u32(smh);
    const int qt = (int)gridDim.x - 1 - (int)blockIdx.x;  // long CTAs first
    const int bh = blockIdx.y;
    const int tid = threadIdx.x;
    const int wid = tid >> 5, lane = tid & 31;
    const int gg = lane >> 2, tt = lane & 3;

    const __half* Qg = g_Qh + (size_t)bh * SS * DKK + (size_t)qt * 128 * DKK;
    const __half* Kg = g_Kh + (size_t)bh * SS * DKK;
    const __half* Vg = g_Vh + (size_t)bh * SS * DKK;
    const int nkt = 2 * qt + 2;
    const int row0 = wid * 16;

#define KVSTG(kt, buf) do { \
    uint32_t _b = sbase + (uint32_t)(buf) * KV_S \
                + (uint32_t)(tid >> 2) * 144u + (uint32_t)(tid & 3) * 32u; \
    const __half* _k = Kg + (size_t)(kt) * 4096 + (tid >> 2) * 64 + (tid & 3) * 16; \
    const __half* _v = Vg + (size_t)(kt) * 4096 + (tid >> 2) * 64 + (tid & 3) * 16; \
    cp16(_b, _k); cp16(_b + 16u, _k + 8); \
    cp16(_b + KV_T, _v); cp16(_b + KV_T + 16u, _v + 8); } while (0)

    KVSTG(0, 0); cp_commit();

    // Q fragments: direct LDG (one-time; Q pre-scaled by QSCALE)
    uint32_t qf[4][4];
    const __half* qbase = Qg + (row0 + gg) * 64 + 2 * tt;
#pragma unroll
    for (int ks = 0; ks < 4; ks++) {
        qf[ks][0] = *(const uint32_t*)(qbase + 16 * ks);
        qf[ks][1] = *(const uint32_t*)(qbase + 16 * ks + 8 * 64);
        qf[ks][2] = *(const uint32_t*)(qbase + 16 * ks + 8);
        qf[ks][3] = *(const uint32_t*)(qbase + 16 * ks + 8 + 8 * 64);
    }

    float o[8][4];
#pragma unroll
    for (int i = 0; i < 8; i++)
#pragma unroll
        for (int j = 0; j < 4; j++) o[i][j] = 0.f;
    float ol[4] = {0.f, 0.f, 0.f, 0.f};   // row-sum accumulator (ones-column)
    const int qrow0 = qt * 128 + row0 + gg;
    const int rowmax = qt * 128 + row0 + 15;   // warp-uniform last row

    const uint32_t kfrag0 = sbase
        + (uint32_t)((lane & 7) * 144 + (lane >> 3) * 16);
    const uint32_t vfrag0 = sbase + KV_T + (uint32_t)((lane & 31) * 144);

    for (int kt = 0; kt < nkt; kt++) {
        cp_wait<0>();
        __syncthreads();
        if (kt + 1 < nkt) { KVSTG(kt + 1, (kt + 1) & 1); cp_commit(); }

        if (kt * 64 > rowmax) continue;   // whole tile above diagonal (uniform)

        const uint32_t kb0 = kfrag0 + (uint32_t)(kt & 1) * KV_S;
        const uint32_t vb0 = vfrag0 + (uint32_t)(kt & 1) * KV_S;
        const bool diag = (kt >= 2 * qt);

        // two independent 32-key halves
#pragma unroll
        for (int h = 0; h < 2; h++) {
            if (kt * 64 + h * 32 > rowmax) continue;   // dead half (uniform)

            // --- QK for nt = 4h .. 4h+3 ---
            float sa[4][4];
#pragma unroll
            for (int i = 0; i < 4; i++)
#pragma unroll
                for (int j = 0; j < 4; j++) sa[i][j] = 0.f;

#pragma unroll
            for (int j = 0; j < 4; j++) {
                const int nt = 4 * h + j;
                if (kt * 64 + nt * 8 > rowmax) continue;   // dead nt block
                uint32_t kb[8];
                ldm4(kb,     kb0 + (uint32_t)nt * 1152u);
                ldm4(kb + 4, kb0 + (uint32_t)nt * 1152u + 64u);
#pragma unroll
                for (int ks = 0; ks < 4; ks++)
                    mma_f16(sa[j], qf[ks], kb[2*ks], kb[2*ks+1]);
            }

            if (diag) {
#pragma unroll
                for (int j = 0; j < 4; j++) {
                    int key = kt * 64 + (4 * h + j) * 8 + 2 * tt;
                    if (key     > qrow0)     sa[j][0] = -INFINITY;
                    if (key + 1 > qrow0)     sa[j][1] = -INFINITY;
                    if (key     > qrow0 + 8) sa[j][2] = -INFINITY;
                    if (key + 1 > qrow0 + 8) sa[j][3] = -INFINITY;
                }
            }

            // --- P = exp2(s) packed fp16 = PV A-frags (ks = 2h, 2h+1) ---
            uint32_t paf[2][4];
#pragma unroll
            for (int p = 0; p < 2; p++) {
                paf[p][0] = ex2h2(h2pack(sa[2*p][0],   sa[2*p][1]));
                paf[p][1] = ex2h2(h2pack(sa[2*p][2],   sa[2*p][3]));
                paf[p][2] = ex2h2(h2pack(sa[2*p+1][0], sa[2*p+1][1]));
                paf[p][3] = ex2h2(h2pack(sa[2*p+1][2], sa[2*p+1][3]));
            }

            const bool ks1_live = (kt * 64 + h * 32 + 16 <= rowmax);

            // --- l += P @ ones ---
            mma_f16(ol, paf[0], ONESH2, ONESH2);
            if (ks1_live) mma_f16(ol, paf[1], ONESH2, ONESH2);

            // --- O += P @ V (keys 32h..32h+31; one ldm4t per dk tile) ---
#pragma unroll
            for (int nt = 0; nt < 8; nt++) {
                uint32_t vb[4];
                ldm4t(vb, vb0 + (uint32_t)nt * 16u + (uint32_t)h * (32u * 144u));
                mma_f16(o[nt], paf[0], vb[0], vb[1]);
                if (ks1_live) mma_f16(o[nt], paf[1], vb[2], vb[3]);
            }
        }
    }
#undef KVSTG

    // ol[0] / ol[2] hold the COMPLETE row sums (mma reduced over k)
    const float inv0 = 1.f / ol[0], inv1 = 1.f / ol[2];

    // Epilogue: g_attnh[b][s][h*64+dk] fp16
    const int b = bh >> 4;
    const int h = bh & 15;
    const int srow0 = qt * 128 + row0 + gg;
#pragma unroll
    for (int nt = 0; nt < 8; nt++) {
        const int dk = nt * 8 + 2 * tt;
        size_t i0 = ((size_t)(b * SS + srow0)) * DD + h * 64 + dk;
        size_t i1 = i0 + (size_t)8 * DD;
        *(uint32_t*)(g_attnh + i0) = h2pack(o[nt][0] * inv0, o[nt][1] * inv0);
        *(uint32_t*)(g_attnh + i1) = h2pack(o[nt][2] * inv1, o[nt][3] * inv1);
    }
}

// ---------------------------------------------------------------------------
extern "C" void kernel_launch(void* const* d_in, const int* in_sizes, int n_in,
                              void* d_out, int out_size)
{
    const float* query = (const float*)d_in[0];
    const float* key_  = (const float*)d_in[1];
    const float* value = (const float*)d_in[2];
    // d_in[3] = mask: causal (tril) -> handled structurally
    const float* W_q = (const float*)d_in[4];
    const float* b_q = (const float*)d_in[5];
    const float* W_k = (const float*)d_in[6];
    const float* b_k = (const float*)d_in[7];
    const float* W_v = (const float*)d_in[8];
    const float* b_v = (const float*)d_in[9];
    const float* W_o = (const float*)d_in[10];
    const float* b_o = (const float*)d_in[11];

    __half *Qh, *Kh, *Vh, *Ah, *xq, *xk, *xv, *wh;
    cudaGetSymbolAddress((void**)&Qh, g_Qh);
    cudaGetSymbolAddress((void**)&Kh, g_Kh);
    cudaGetSymbolAddress((void**)&Vh, g_Vh);
    cudaGetSymbolAddress((void**)&Ah, g_attnh);
    cudaGetSymbolAddress((void**)&xq, g_xq);
    cudaGetSymbolAddress((void**)&xk, g_xk);
    cudaGetSymbolAddress((void**)&xv, g_xv);
    cudaGetSymbolAddress((void**)&wh, g_wh);

    const int NIN = BB * SS * DD;   // 4M
    const int NW  = DD * DD;        // 1M

    cvt_all<<<dim3(512, 1, 7), 256>>>(xq, xk, xv, wh,
                                      query, key_, value,
                                      W_q, W_k, W_v, W_o,
                                      NIN / 4, NW / 4);

    cudaFuncSetAttribute(attn_h,
                         cudaFuncAttributeMaxDynamicSharedMemorySize, ATT_SMEM);

    gemm_qkv<<<dim3(8, 32, 3), 256>>>(xq, xk, xv, wh,
                                      b_q, b_k, b_v, Qh, Kh, Vh);

    attn_h<<<dim3(SS / 128, BB * HH), 256, ATT_SMEM>>>();

    gemm_out<<<dim3(8, 32), 256>>>(Ah, wh + (size_t)3 * NW,
                                   b_o, (float*)d_out);
}

// round 14
// speedup vs baseline: 2.0000x; 2.0000x over previous
#include <cuda_runtime.h>
#include <cuda_fp16.h>
#include <math.h>
#include <stdint.h>

#define BB 2
#define SS 2048
#define DD 1024
#define HH 16
#define DKK 64

// Q pre-scale: 1/sqrt(64) * log2(e)  (softmax runs in exp2 domain)
#define QSCALE 0.1803368801111204f
#define ONESH2 0x3C003C00u          // fp16x2 {1.0, 1.0}

// Scratch (allocation-free rule: __device__ globals)
__device__ __half g_Qh[BB*HH*SS*DKK];     // [b][h][s][dk] fp16, pre-scaled
__device__ __half g_Kh[BB*HH*SS*DKK];
__device__ __half g_Vh[BB*HH*SS*DKK];
__device__ __half g_attnh[BB*SS*DD];      // [b][s][h*64+dk] fp16
__device__ __half g_xq[BB*SS*DD];         // fp16 inputs
__device__ __half g_xk[BB*SS*DD];
__device__ __half g_xv[BB*SS*DD];
__device__ __half g_wh[4*DD*DD];          // fp16 W_q,W_k,W_v,W_o

__device__ __forceinline__ uint32_t smem_u32(const void* p) {
    uint32_t a;
    asm("{ .reg .u64 t; cvta.to.shared.u64 t, %1; cvt.u32.u64 %0, t; }"
        : "=r"(a) : "l"(p));
    return a;
}
__device__ __forceinline__ void cp16(uint32_t saddr, const void* g) {
    asm volatile("cp.async.cg.shared.global [%0], [%1], 16;"
                 :: "r"(saddr), "l"(g) : "memory");
}
__device__ __forceinline__ void cp_commit() {
    asm volatile("cp.async.commit_group;" ::: "memory");
}
template<int N> __device__ __forceinline__ void cp_wait() {
    asm volatile("cp.async.wait_group %0;" :: "n"(N) : "memory");
}
__device__ __forceinline__ void ldm4(uint32_t* r, uint32_t addr) {
    asm volatile("ldmatrix.sync.aligned.m8n8.x4.shared.b16 {%0,%1,%2,%3}, [%4];"
        : "=r"(r[0]), "=r"(r[1]), "=r"(r[2]), "=r"(r[3]) : "r"(addr));
}
__device__ __forceinline__ void ldm4t(uint32_t* r, uint32_t addr) {
    asm volatile("ldmatrix.sync.aligned.m8n8.x4.trans.shared.b16 {%0,%1,%2,%3}, [%4];"
        : "=r"(r[0]), "=r"(r[1]), "=r"(r[2]), "=r"(r[3]) : "r"(addr));
}
__device__ __forceinline__ void mma_f16(float* d, const uint32_t* a,
                                        uint32_t b0, uint32_t b1)
{
    asm volatile(
        "mma.sync.aligned.m16n8k16.row.col.f32.f16.f16.f32 "
        "{%0,%1,%2,%3}, {%4,%5,%6,%7}, {%8,%9}, {%0,%1,%2,%3};"
        : "+f"(d[0]), "+f"(d[1]), "+f"(d[2]), "+f"(d[3])
        : "r"(a[0]), "r"(a[1]), "r"(a[2]), "r"(a[3]), "r"(b0), "r"(b1));
}
__device__ __forceinline__ uint32_t h2pack(float x, float y) {
    __half2 h = __floats2half2_rn(x, y);
    return *reinterpret_cast<uint32_t*>(&h);
}
__device__ __forceinline__ uint32_t ex2h2(uint32_t x) {
    uint32_t r; asm("ex2.approx.f16x2 %0, %1;" : "=r"(r) : "r"(x)); return r;
}

// ===========================================================================
// Prepass: fp32 -> fp16 (RN), single launch (z selects tensor)
// ===========================================================================
__global__ void cvt_all(__half* xq, __half* xk, __half* xv, __half* wh,
                        const float* q, const float* k, const float* v,
                        const float* w0, const float* w1,
                        const float* w2, const float* w3,
                        int n4_in, int n4_w)
{
    const int z = blockIdx.z;
    const float* s;
    __half* d;
    int n4;
    if (z < 3) {
        s = z == 0 ? q : z == 1 ? k : v;
        d = z == 0 ? xq : z == 1 ? xk : xv;
        n4 = n4_in;
    } else {
        s = z == 3 ? w0 : z == 4 ? w1 : z == 5 ? w2 : w3;
        d = wh + (size_t)(z - 3) * (size_t)n4_w * 4;
        n4 = n4_w;
    }
    int i = blockIdx.x * blockDim.x + threadIdx.x;
    int str = gridDim.x * blockDim.x;
    for (; i < n4; i += str) {
        float4 vv = ((const float4*)s)[i];
        uint2 u;
        u.x = h2pack(vv.x, vv.y);
        u.y = h2pack(vv.z, vv.w);
        ((uint2*)d)[i] = u;
    }
}

// ===========================================================================
// fp16 GEMM (R14): cp.async + ldmatrix (R12 machinery), tile 128(M)x256(N),
// 512 threads (16 warps, 4x4; warp = 32x64). Stages A(128)+W(256)=384 rows
// per tile vs 512 for two 128x128 tiles: 25% fewer LDGSTS (the measured
// bottleneck, rt=8cyc/16B/SMSP). 3-stage pipeline, prefetch distance 2.
// W smem region starts at 10240 = 128*80 so dst = stage + row*80 uniformly.
// ===========================================================================
#define G_STAGE 30720u            // 384 rows * 80B
#define GEMM_SMEM (3 * 30720)     // 92160 B

template<bool REORDER>
__device__ __forceinline__ void gemm_body(const __half* __restrict__ A,
                                          const __half* __restrict__ W,
                                          const float* __restrict__ bias,
                                          void* Cout, float oscale)
{
    extern __shared__ __half smh[];
    const uint32_t sbase = smem_u32(smh);
    const int tid = threadIdx.x;
    const int bm = blockIdx.y * 128;
    const int bn = blockIdx.x * 256;
    const int wid = tid >> 5, lane = tid & 31;
    const int warpM = wid >> 2, warpN = wid & 3;   // 4 x 4 warps
    const int gg = lane >> 2, tt = lane & 3;

// staging: 1536 cp16 tasks per chunk; thread does 3 (task = it*512 + tid).
// row = task>>2 (0..383: 0-127 A rows, 128-383 W rows), seg = (task&3)*8 halves
#define GSTG(c) do { \
    _Pragma("unroll") \
    for (int it = 0; it < 3; it++) { \
        int task = it * 512 + tid; \
        int row = task >> 2, seg = (task & 3) * 8; \
        const __half* src = (row < 128) \
            ? A + (size_t)(bm + row) * 1024 + (c) * 32 + seg \
            : W + (size_t)(bn + row - 128) * 1024 + (c) * 32 + seg; \
        cp16(sbase + ((c) % 3) * G_STAGE + (uint32_t)(row * 80 + seg * 2), src); \
    } } while (0)

    GSTG(0); cp_commit();
    GSTG(1); cp_commit();

    float acc[16][4];
#pragma unroll
    for (int i = 0; i < 16; i++)
#pragma unroll
        for (int j = 0; j < 4; j++) acc[i][j] = 0.f;

    const uint32_t abase0 = sbase
        + (uint32_t)((warpM * 32 + (lane & 15)) * 80 + (lane >> 4) * 16);
    const uint32_t bbase0 = sbase + 10240u
        + (uint32_t)((warpN * 64 + (lane & 7)) * 80 + (lane >> 3) * 16);

    for (int c = 0; c < 32; c++) {
        cp_wait<1>();
        __syncthreads();
        if (c + 2 < 32) GSTG(c + 2);
        cp_commit();

        const uint32_t stg = (uint32_t)(c % 3) * G_STAGE;
        uint32_t bf[8][4];
#pragma unroll
        for (int nt = 0; nt < 8; nt++)
            ldm4(bf[nt], bbase0 + stg + (uint32_t)nt * 640u);
#pragma unroll
        for (int ks = 0; ks < 2; ks++) {
            uint32_t af[2][4];
#pragma unroll
            for (int mt = 0; mt < 2; mt++)
                ldm4(af[mt], abase0 + stg + (uint32_t)mt * 1280u + (uint32_t)ks * 32u);
#pragma unroll
            for (int mt = 0; mt < 2; mt++)
#pragma unroll
                for (int nt = 0; nt < 8; nt++)
                    mma_f16(acc[mt*8+nt], af[mt], bf[nt][2*ks], bf[nt][2*ks+1]);
        }
    }
#undef GSTG

#pragma unroll
    for (int mt = 0; mt < 2; mt++) {
#pragma unroll
        for (int nt = 0; nt < 8; nt++) {
            const int n0 = bn + warpN * 64 + nt * 8 + 2 * tt;
            const float2 bb = *(const float2*)(bias + n0);
#pragma unroll
            for (int half = 0; half < 2; half++) {
                const int m = bm + warpM * 32 + mt * 16 + gg + half * 8;
                float vx = (acc[mt*8+nt][half*2+0] + bb.x) * oscale;
                float vy = (acc[mt*8+nt][half*2+1] + bb.y) * oscale;
                if (REORDER) {
                    const int b = m >> 11, s = m & 2047;
                    const int h = n0 >> 6, dk = n0 & 63;
                    size_t idx = ((size_t)(b * HH + h) * SS + s) * DKK + dk;
                    *(uint32_t*)((__half*)Cout + idx) = h2pack(vx, vy);
                } else {
                    size_t idx = (size_t)m * DD + n0;
                    *(float2*)((float*)Cout + idx) = make_float2(vx, vy);
                }
            }
        }
    }
}

__global__ void __launch_bounds__(512, 1)
gemm_qkv(const __half* xq, const __half* xk, const __half* xv,
         const __half* w4,
         const float* bq, const float* bk, const float* bv,
         __half* oq, __half* ok, __half* ov)
{
    const int z = blockIdx.z;
    const __half* A = z == 0 ? xq : z == 1 ? xk : xv;
    const __half* W = w4 + (size_t)z * DD * DD;
    const float* bias = z == 0 ? bq : z == 1 ? bk : bv;
    __half* out = z == 0 ? oq : z == 1 ? ok : ov;
    gemm_body<true>(A, W, bias, out, z == 0 ? QSCALE : 1.0f);
}

__global__ void __launch_bounds__(512, 1)
gemm_out(const __half* A, const __half* W, const float* bias, float* C)
{
    gemm_body<false>(A, W, bias, C, 1.0f);
}

// ===========================================================================
// Flash attention (EXACT R12 — proven best): fp16 mma, causal, max-free
// exp2 softmax, split-half pipelining, ones-column l on the tensor pipe.
// ===========================================================================
#define KV_T 9216u        // bytes per tensor tile: 64 * 144
#define KV_S 18432u       // bytes per stage (K+V)
#define ATT_SMEM (2 * 18432)   // 36864 B

__global__ void __launch_bounds__(256, 2)
attn_h()
{
    extern __shared__ __half smh[];
    const uint32_t sbase = smem_u32(smh);
    const int qt = (int)gridDim.x - 1 - (int)blockIdx.x;  // long CTAs first
    const int bh = blockIdx.y;
    const int tid = threadIdx.x;
    const int wid = tid >> 5, lane = tid & 31;
    const int gg = lane >> 2, tt = lane & 3;

    const __half* Qg = g_Qh + (size_t)bh * SS * DKK + (size_t)qt * 128 * DKK;
    const __half* Kg = g_Kh + (size_t)bh * SS * DKK;
    const __half* Vg = g_Vh + (size_t)bh * SS * DKK;
    const int nkt = 2 * qt + 2;
    const int row0 = wid * 16;

#define KVSTG(kt, buf) do { \
    uint32_t _b = sbase + (uint32_t)(buf) * KV_S \
                + (uint32_t)(tid >> 2) * 144u + (uint32_t)(tid & 3) * 32u; \
    const __half* _k = Kg + (size_t)(kt) * 4096 + (tid >> 2) * 64 + (tid & 3) * 16; \
    const __half* _v = Vg + (size_t)(kt) * 4096 + (tid >> 2) * 64 + (tid & 3) * 16; \
    cp16(_b, _k); cp16(_b + 16u, _k + 8); \
    cp16(_b + KV_T, _v); cp16(_b + KV_T + 16u, _v + 8); } while (0)

    KVSTG(0, 0); cp_commit();

    // Q fragments: direct LDG (one-time; Q pre-scaled by QSCALE)
    uint32_t qf[4][4];
    const __half* qbase = Qg + (row0 + gg) * 64 + 2 * tt;
#pragma unroll
    for (int ks = 0; ks < 4; ks++) {
        qf[ks][0] = *(const uint32_t*)(qbase + 16 * ks);
        qf[ks][1] = *(const uint32_t*)(qbase + 16 * ks + 8 * 64);
        qf[ks][2] = *(const uint32_t*)(qbase + 16 * ks + 8);
        qf[ks][3] = *(const uint32_t*)(qbase + 16 * ks + 8 + 8 * 64);
    }

    float o[8][4];
#pragma unroll
    for (int i = 0; i < 8; i++)
#pragma unroll
        for (int j = 0; j < 4; j++) o[i][j] = 0.f;
    float ol[4] = {0.f, 0.f, 0.f, 0.f};   // row-sum accumulator (ones-column)
    const int qrow0 = qt * 128 + row0 + gg;
    const int rowmax = qt * 128 + row0 + 15;   // warp-uniform last row

    const uint32_t kfrag0 = sbase
        + (uint32_t)((lane & 7) * 144 + (lane >> 3) * 16);
    const uint32_t vfrag0 = sbase + KV_T + (uint32_t)((lane & 31) * 144);

    for (int kt = 0; kt < nkt; kt++) {
        cp_wait<0>();
        __syncthreads();
        if (kt + 1 < nkt) { KVSTG(kt + 1, (kt + 1) & 1); cp_commit(); }

        if (kt * 64 > rowmax) continue;   // whole tile above diagonal (uniform)

        const uint32_t kb0 = kfrag0 + (uint32_t)(kt & 1) * KV_S;
        const uint32_t vb0 = vfrag0 + (uint32_t)(kt & 1) * KV_S;
        const bool diag = (kt >= 2 * qt);

        // two independent 32-key halves
#pragma unroll
        for (int h = 0; h < 2; h++) {
            if (kt * 64 + h * 32 > rowmax) continue;   // dead half (uniform)

            // --- QK for nt = 4h .. 4h+3 ---
            float sa[4][4];
#pragma unroll
            for (int i = 0; i < 4; i++)
#pragma unroll
                for (int j = 0; j < 4; j++) sa[i][j] = 0.f;

#pragma unroll
            for (int j = 0; j < 4; j++) {
                const int nt = 4 * h + j;
                if (kt * 64 + nt * 8 > rowmax) continue;   // dead nt block
                uint32_t kb[8];
                ldm4(kb,     kb0 + (uint32_t)nt * 1152u);
                ldm4(kb + 4, kb0 + (uint32_t)nt * 1152u + 64u);
#pragma unroll
                for (int ks = 0; ks < 4; ks++)
                    mma_f16(sa[j], qf[ks], kb[2*ks], kb[2*ks+1]);
            }

            if (diag) {
#pragma unroll
                for (int j = 0; j < 4; j++) {
                    int key = kt * 64 + (4 * h + j) * 8 + 2 * tt;
                    if (key     > qrow0)     sa[j][0] = -INFINITY;
                    if (key + 1 > qrow0)     sa[j][1] = -INFINITY;
                    if (key     > qrow0 + 8) sa[j][2] = -INFINITY;
                    if (key + 1 > qrow0 + 8) sa[j][3] = -INFINITY;
                }
            }

            // --- P = exp2(s) packed fp16 = PV A-frags (ks = 2h, 2h+1) ---
            uint32_t paf[2][4];
#pragma unroll
            for (int p = 0; p < 2; p++) {
                paf[p][0] = ex2h2(h2pack(sa[2*p][0],   sa[2*p][1]));
                paf[p][1] = ex2h2(h2pack(sa[2*p][2],   sa[2*p][3]));
                paf[p][2] = ex2h2(h2pack(sa[2*p+1][0], sa[2*p+1][1]));
                paf[p][3] = ex2h2(h2pack(sa[2*p+1][2], sa[2*p+1][3]));
            }

            const bool ks1_live = (kt * 64 + h * 32 + 16 <= rowmax);

            // --- l += P @ ones ---
            mma_f16(ol, paf[0], ONESH2, ONESH2);
            if (ks1_live) mma_f16(ol, paf[1], ONESH2, ONESH2);

            // --- O += P @ V (keys 32h..32h+31; one ldm4t per dk tile) ---
#pragma unroll
            for (int nt = 0; nt < 8; nt++) {
                uint32_t vb[4];
                ldm4t(vb, vb0 + (uint32_t)nt * 16u + (uint32_t)h * (32u * 144u));
                mma_f16(o[nt], paf[0], vb[0], vb[1]);
                if (ks1_live) mma_f16(o[nt], paf[1], vb[2], vb[3]);
            }
        }
    }
#undef KVSTG

    // ol[0] / ol[2] hold the COMPLETE row sums (mma reduced over k)
    const float inv0 = 1.f / ol[0], inv1 = 1.f / ol[2];

    // Epilogue: g_attnh[b][s][h*64+dk] fp16
    const int b = bh >> 4;
    const int h = bh & 15;
    const int srow0 = qt * 128 + row0 + gg;
#pragma unroll
    for (int nt = 0; nt < 8; nt++) {
        const int dk = nt * 8 + 2 * tt;
        size_t i0 = ((size_t)(b * SS + srow0)) * DD + h * 64 + dk;
        size_t i1 = i0 + (size_t)8 * DD;
        *(uint32_t*)(g_attnh + i0) = h2pack(o[nt][0] * inv0, o[nt][1] * inv0);
        *(uint32_t*)(g_attnh + i1) = h2pack(o[nt][2] * inv1, o[nt][3] * inv1);
    }
}

// ---------------------------------------------------------------------------
extern "C" void kernel_launch(void* const* d_in, const int* in_sizes, int n_in,
                              void* d_out, int out_size)
{
    const float* query = (const float*)d_in[0];
    const float* key_  = (const float*)d_in[1];
    const float* value = (const float*)d_in[2];
    // d_in[3] = mask: causal (tril) -> handled structurally
    const float* W_q = (const float*)d_in[4];
    const float* b_q = (const float*)d_in[5];
    const float* W_k = (const float*)d_in[6];
    const float* b_k = (const float*)d_in[7];
    const float* W_v = (const float*)d_in[8];
    const float* b_v = (const float*)d_in[9];
    const float* W_o = (const float*)d_in[10];
    const float* b_o = (const float*)d_in[11];

    __half *Qh, *Kh, *Vh, *Ah, *xq, *xk, *xv, *wh;
    cudaGetSymbolAddress((void**)&Qh, g_Qh);
    cudaGetSymbolAddress((void**)&Kh, g_Kh);
    cudaGetSymbolAddress((void**)&Vh, g_Vh);
    cudaGetSymbolAddress((void**)&Ah, g_attnh);
    cudaGetSymbolAddress((void**)&xq, g_xq);
    cudaGetSymbolAddress((void**)&xk, g_xk);
    cudaGetSymbolAddress((void**)&xv, g_xv);
    cudaGetSymbolAddress((void**)&wh, g_wh);

    const int NIN = BB * SS * DD;   // 4M
    const int NW  = DD * DD;        // 1M

    cvt_all<<<dim3(512, 1, 7), 256>>>(xq, xk, xv, wh,
                                      query, key_, value,
                                      W_q, W_k, W_v, W_o,
                                      NIN / 4, NW / 4);

    cudaFuncSetAttribute(gemm_qkv,
                         cudaFuncAttributeMaxDynamicSharedMemorySize, GEMM_SMEM);
    cudaFuncSetAttribute(gemm_out,
                         cudaFuncAttributeMaxDynamicSharedMemorySize, GEMM_SMEM);
    cudaFuncSetAttribute(attn_h,
                         cudaFuncAttributeMaxDynamicSharedMemorySize, ATT_SMEM);

    gemm_qkv<<<dim3(4, 32, 3), 512, GEMM_SMEM>>>(xq, xk, xv, wh,
                                                 b_q, b_k, b_v, Qh, Kh, Vh);

    attn_h<<<dim3(SS / 128, BB * HH), 256, ATT_SMEM>>>();

    gemm_out<<<dim3(4, 32), 512, GEMM_SMEM>>>(Ah, wh + (size_t)3 * NW,
                                              b_o, (float*)d_out);
}

// round 16
// speedup vs baseline: 2.1782x; 1.0891x over previous
#include <cuda_runtime.h>
#include <cuda_fp16.h>
#include <math.h>
#include <stdint.h>

#define BB 2
#define SS 2048
#define DD 1024
#define HH 16
#define DKK 64

// Q pre-scale: 1/sqrt(64) * log2(e)  (softmax runs in exp2 domain)
#define QSCALE 0.1803368801111204f
#define ONESH2 0x3C003C00u          // fp16x2 {1.0, 1.0}

// Scratch (allocation-free rule: __device__ globals)
__device__ __half g_Qh[BB*HH*SS*DKK];     // [b][h][s][dk] fp16, pre-scaled
__device__ __half g_Kh[BB*HH*SS*DKK];
__device__ __half g_Vh[BB*HH*SS*DKK];
__device__ __half g_attnh[BB*SS*DD];      // [b][s][h*64+dk] fp16
__device__ __half g_xq[BB*SS*DD];         // fp16 inputs
__device__ __half g_xk[BB*SS*DD];
__device__ __half g_xv[BB*SS*DD];
__device__ __half g_wh[4*DD*DD];          // fp16 W_q,W_k,W_v,W_o

__device__ __forceinline__ uint32_t smem_u32(const void* p) {
    uint32_t a;
    asm("{ .reg .u64 t; cvta.to.shared.u64 t, %1; cvt.u32.u64 %0, t; }"
        : "=r"(a) : "l"(p));
    return a;
}
__device__ __forceinline__ void cp16(uint32_t saddr, const void* g) {
    asm volatile("cp.async.cg.shared.global [%0], [%1], 16;"
                 :: "r"(saddr), "l"(g) : "memory");
}
__device__ __forceinline__ void cp_commit() {
    asm volatile("cp.async.commit_group;" ::: "memory");
}
template<int N> __device__ __forceinline__ void cp_wait() {
    asm volatile("cp.async.wait_group %0;" :: "n"(N) : "memory");
}
__device__ __forceinline__ void ldm4(uint32_t* r, uint32_t addr) {
    asm volatile("ldmatrix.sync.aligned.m8n8.x4.shared.b16 {%0,%1,%2,%3}, [%4];"
        : "=r"(r[0]), "=r"(r[1]), "=r"(r[2]), "=r"(r[3]) : "r"(addr));
}
__device__ __forceinline__ void ldm4t(uint32_t* r, uint32_t addr) {
    asm volatile("ldmatrix.sync.aligned.m8n8.x4.trans.shared.b16 {%0,%1,%2,%3}, [%4];"
        : "=r"(r[0]), "=r"(r[1]), "=r"(r[2]), "=r"(r[3]) : "r"(addr));
}
__device__ __forceinline__ void mma_f16(float* d, const uint32_t* a,
                                        uint32_t b0, uint32_t b1)
{
    asm volatile(
        "mma.sync.aligned.m16n8k16.row.col.f32.f16.f16.f32 "
        "{%0,%1,%2,%3}, {%4,%5,%6,%7}, {%8,%9}, {%0,%1,%2,%3};"
        : "+f"(d[0]), "+f"(d[1]), "+f"(d[2]), "+f"(d[3])
        : "r"(a[0]), "r"(a[1]), "r"(a[2]), "r"(a[3]), "r"(b0), "r"(b1));
}
__device__ __forceinline__ uint32_t h2pack(float x, float y) {
    __half2 h = __floats2half2_rn(x, y);
    return *reinterpret_cast<uint32_t*>(&h);
}
__device__ __forceinline__ uint32_t ex2h2(uint32_t x) {
    uint32_t r; asm("ex2.approx.f16x2 %0, %1;" : "=r"(r) : "r"(x)); return r;
}

// ===========================================================================
// Prepass: fp32 -> fp16 (RN), single launch; MLP=4.
// FIXED (R16): base = blockIdx.x*blockDim.x + tid (R15 used *4, leaving 3/4
// of every tensor unconverted). Coverage: base + j*span, step span*4.
// ===========================================================================
__global__ void cvt_all(__half* xq, __half* xk, __half* xv, __half* wh,
                        const float* q, const float* k, const float* v,
                        const float* w0, const float* w1,
                        const float* w2, const float* w3,
                        int n4_in, int n4_w)
{
    const int z = blockIdx.z;
    const float* s;
    __half* d;
    int n4;
    if (z < 3) {
        s = z == 0 ? q : z == 1 ? k : v;
        d = z == 0 ? xq : z == 1 ? xk : xv;
        n4 = n4_in;
    } else {
        s = z == 3 ? w0 : z == 4 ? w1 : z == 5 ? w2 : w3;
        d = wh + (size_t)(z - 3) * (size_t)n4_w * 4;
        n4 = n4_w;
    }
    const int span = gridDim.x * blockDim.x;       // threads per z-slice
    for (int base = blockIdx.x * blockDim.x + threadIdx.x;
         base < n4; base += span * 4) {
        float4 v4[4];
        bool ok[4];
#pragma unroll
        for (int j = 0; j < 4; j++) {
            int i = base + j * span;
            ok[j] = i < n4;
            if (ok[j]) v4[j] = ((const float4*)s)[i];
        }
#pragma unroll
        for (int j = 0; j < 4; j++) {
            if (ok[j]) {
                int i = base + j * span;
                uint2 u;
                u.x = h2pack(v4[j].x, v4[j].y);
                u.y = h2pack(v4[j].z, v4[j].w);
                ((uint2*)d)[i] = u;
            }
        }
    }
}

// ===========================================================================
// fp16 GEMM (R15 design, unchanged): cp.async + ldmatrix, 128(M)x256(N),
// 512 threads, K chunk 64 (two 32-K register halves), 3-stage pipeline
// (prefetch distance 2 chunks). smem rows: 128B data + 16B pad (144B stride).
// ===========================================================================
#define G_STAGE 55296u            // 384 rows * 144B
#define GEMM_SMEM (3 * 55296)     // 165888 B

template<bool REORDER>
__device__ __forceinline__ void gemm_body(const __half* __restrict__ A,
                                          const __half* __restrict__ W,
                                          const float* __restrict__ bias,
                                          void* Cout, float oscale)
{
    extern __shared__ __half smh[];
    const uint32_t sbase = smem_u32(smh);
    const int tid = threadIdx.x;
    const int bm = blockIdx.y * 128;
    const int bn = blockIdx.x * 256;
    const int wid = tid >> 5, lane = tid & 31;
    const int warpM = wid >> 2, warpN = wid & 3;   // 4 x 4 warps
    const int gg = lane >> 2, tt = lane & 3;

// staging: 3072 cp16 tasks per chunk (384 rows x 8); thread does 6.
// row = task>>3 (0-127 A rows, 128-383 W rows), seg = (task&7)*8 halves
#define GSTG(c) do { \
    _Pragma("unroll") \
    for (int it = 0; it < 6; it++) { \
        int task = it * 512 + tid; \
        int row = task >> 3, seg = (task & 7) * 8; \
        const __half* src = (row < 128) \
            ? A + (size_t)(bm + row) * 1024 + (c) * 64 + seg \
            : W + (size_t)(bn + row - 128) * 1024 + (c) * 64 + seg; \
        cp16(sbase + ((c) % 3) * G_STAGE + (uint32_t)(row * 144 + seg * 2), src); \
    } } while (0)

    GSTG(0); cp_commit();
    GSTG(1); cp_commit();

    float acc[16][4];
#pragma unroll
    for (int i = 0; i < 16; i++)
#pragma unroll
        for (int j = 0; j < 4; j++) acc[i][j] = 0.f;

    const uint32_t abase0 = sbase
        + (uint32_t)((warpM * 32 + (lane & 15)) * 144 + (lane >> 4) * 16);
    const uint32_t bbase0 = sbase + 18432u       // 128 * 144
        + (uint32_t)((warpN * 64 + (lane & 7)) * 144 + (lane >> 3) * 16);

    for (int c = 0; c < 16; c++) {
        cp_wait<1>();
        __syncthreads();
        if (c + 2 < 16) GSTG(c + 2);
        cp_commit();

        const uint32_t stg = (uint32_t)(c % 3) * G_STAGE;
        // two 32-K halves per chunk (byte offset h*64 within the row)
#pragma unroll
        for (int h = 0; h < 2; h++) {
            const uint32_t hb = stg + (uint32_t)h * 64u;
            uint32_t bf[8][4];
#pragma unroll
            for (int nt = 0; nt < 8; nt++)
                ldm4(bf[nt], bbase0 + hb + (uint32_t)nt * 1152u);
#pragma unroll
            for (int ks = 0; ks < 2; ks++) {
                uint32_t af[2][4];
#pragma unroll
                for (int mt = 0; mt < 2; mt++)
                    ldm4(af[mt], abase0 + hb + (uint32_t)mt * 2304u
                                 + (uint32_t)ks * 32u);
#pragma unroll
                for (int mt = 0; mt < 2; mt++)
#pragma unroll
                    for (int nt = 0; nt < 8; nt++)
                        mma_f16(acc[mt*8+nt], af[mt],
                                bf[nt][2*ks], bf[nt][2*ks+1]);
            }
        }
    }
#undef GSTG

#pragma unroll
    for (int mt = 0; mt < 2; mt++) {
#pragma unroll
        for (int nt = 0; nt < 8; nt++) {
            const int n0 = bn + warpN * 64 + nt * 8 + 2 * tt;
            const float2 bb = *(const float2*)(bias + n0);
#pragma unroll
            for (int half = 0; half < 2; half++) {
                const int m = bm + warpM * 32 + mt * 16 + gg + half * 8;
                float vx = (acc[mt*8+nt][half*2+0] + bb.x) * oscale;
                float vy = (acc[mt*8+nt][half*2+1] + bb.y) * oscale;
                if (REORDER) {
                    const int b = m >> 11, s = m & 2047;
                    const int h = n0 >> 6, dk = n0 & 63;
                    size_t idx = ((size_t)(b * HH + h) * SS + s) * DKK + dk;
                    *(uint32_t*)((__half*)Cout + idx) = h2pack(vx, vy);
                } else {
                    size_t idx = (size_t)m * DD + n0;
                    *(float2*)((float*)Cout + idx) = make_float2(vx, vy);
                }
            }
        }
    }
}

__global__ void __launch_bounds__(512, 1)
gemm_qkv(const __half* xq, const __half* xk, const __half* xv,
         const __half* w4,
         const float* bq, const float* bk, const float* bv,
         __half* oq, __half* ok, __half* ov)
{
    const int z = blockIdx.z;
    const __half* A = z == 0 ? xq : z == 1 ? xk : xv;
    const __half* W = w4 + (size_t)z * DD * DD;
    const float* bias = z == 0 ? bq : z == 1 ? bk : bv;
    __half* out = z == 0 ? oq : z == 1 ? ok : ov;
    gemm_body<true>(A, W, bias, out, z == 0 ? QSCALE : 1.0f);
}

__global__ void __launch_bounds__(512, 1)
gemm_out(const __half* A, const __half* W, const float* bias, float* C)
{
    gemm_body<false>(A, W, bias, C, 1.0f);
}

// ===========================================================================
// Flash attention (EXACT R12 — proven best): fp16 mma, causal, max-free
// exp2 softmax, split-half pipelining, ones-column l on the tensor pipe.
// ===========================================================================
#define KV_T 9216u        // bytes per tensor tile: 64 * 144
#define KV_S 18432u       // bytes per stage (K+V)
#define ATT_SMEM (2 * 18432)   // 36864 B

__global__ void __launch_bounds__(256, 2)
attn_h()
{
    extern __shared__ __half smh[];
    const uint32_t sbase = smem_u32(smh);
    const int qt = (int)gridDim.x - 1 - (int)blockIdx.x;  // long CTAs first
    const int bh = blockIdx.y;
    const int tid = threadIdx.x;
    const int wid = tid >> 5, lane = tid & 31;
    const int gg = lane >> 2, tt = lane & 3;

    const __half* Qg = g_Qh + (size_t)bh * SS * DKK + (size_t)qt * 128 * DKK;
    const __half* Kg = g_Kh + (size_t)bh * SS * DKK;
    const __half* Vg = g_Vh + (size_t)bh * SS * DKK;
    const int nkt = 2 * qt + 2;
    const int row0 = wid * 16;

#define KVSTG(kt, buf) do { \
    uint32_t _b = sbase + (uint32_t)(buf) * KV_S \
                + (uint32_t)(tid >> 2) * 144u + (uint32_t)(tid & 3) * 32u; \
    const __half* _k = Kg + (size_t)(kt) * 4096 + (tid >> 2) * 64 + (tid & 3) * 16; \
    const __half* _v = Vg + (size_t)(kt) * 4096 + (tid >> 2) * 64 + (tid & 3) * 16; \
    cp16(_b, _k); cp16(_b + 16u, _k + 8); \
    cp16(_b + KV_T, _v); cp16(_b + KV_T + 16u, _v + 8); } while (0)

    KVSTG(0, 0); cp_commit();

    // Q fragments: direct LDG (one-time; Q pre-scaled by QSCALE)
    uint32_t qf[4][4];
    const __half* qbase = Qg + (row0 + gg) * 64 + 2 * tt;
#pragma unroll
    for (int ks = 0; ks < 4; ks++) {
        qf[ks][0] = *(const uint32_t*)(qbase + 16 * ks);
        qf[ks][1] = *(const uint32_t*)(qbase + 16 * ks + 8 * 64);
        qf[ks][2] = *(const uint32_t*)(qbase + 16 * ks + 8);
        qf[ks][3] = *(const uint32_t*)(qbase + 16 * ks + 8 + 8 * 64);
    }

    float o[8][4];
#pragma unroll
    for (int i = 0; i < 8; i++)
#pragma unroll
        for (int j = 0; j < 4; j++) o[i][j] = 0.f;
    float ol[4] = {0.f, 0.f, 0.f, 0.f};   // row-sum accumulator (ones-column)
    const int qrow0 = qt * 128 + row0 + gg;
    const int rowmax = qt * 128 + row0 + 15;   // warp-uniform last row

    const uint32_t kfrag0 = sbase
        + (uint32_t)((lane & 7) * 144 + (lane >> 3) * 16);
    const uint32_t vfrag0 = sbase + KV_T + (uint32_t)((lane & 31) * 144);

    for (int kt = 0; kt < nkt; kt++) {
        cp_wait<0>();
        __syncthreads();
        if (kt + 1 < nkt) { KVSTG(kt + 1, (kt + 1) & 1); cp_commit(); }

        if (kt * 64 > rowmax) continue;   // whole tile above diagonal (uniform)

        const uint32_t kb0 = kfrag0 + (uint32_t)(kt & 1) * KV_S;
        const uint32_t vb0 = vfrag0 + (uint32_t)(kt & 1) * KV_S;
        const bool diag = (kt >= 2 * qt);

        // two independent 32-key halves
#pragma unroll
        for (int h = 0; h < 2; h++) {
            if (kt * 64 + h * 32 > rowmax) continue;   // dead half (uniform)

            // --- QK for nt = 4h .. 4h+3 ---
            float sa[4][4];
#pragma unroll
            for (int i = 0; i < 4; i++)
#pragma unroll
                for (int j = 0; j < 4; j++) sa[i][j] = 0.f;

#pragma unroll
            for (int j = 0; j < 4; j++) {
                const int nt = 4 * h + j;
                if (kt * 64 + nt * 8 > rowmax) continue;   // dead nt block
                uint32_t kb[8];
                ldm4(kb,     kb0 + (uint32_t)nt * 1152u);
                ldm4(kb + 4, kb0 + (uint32_t)nt * 1152u + 64u);
#pragma unroll
                for (int ks = 0; ks < 4; ks++)
                    mma_f16(sa[j], qf[ks], kb[2*ks], kb[2*ks+1]);
            }

            if (diag) {
#pragma unroll
                for (int j = 0; j < 4; j++) {
                    int key = kt * 64 + (4 * h + j) * 8 + 2 * tt;
                    if (key     > qrow0)     sa[j][0] = -INFINITY;
                    if (key + 1 > qrow0)     sa[j][1] = -INFINITY;
                    if (key     > qrow0 + 8) sa[j][2] = -INFINITY;
                    if (key + 1 > qrow0 + 8) sa[j][3] = -INFINITY;
                }
            }

            // --- P = exp2(s) packed fp16 = PV A-frags (ks = 2h, 2h+1) ---
            uint32_t paf[2][4];
#pragma unroll
            for (int p = 0; p < 2; p++) {
                paf[p][0] = ex2h2(h2pack(sa[2*p][0],   sa[2*p][1]));
                paf[p][1] = ex2h2(h2pack(sa[2*p][2],   sa[2*p][3]));
                paf[p][2] = ex2h2(h2pack(sa[2*p+1][0], sa[2*p+1][1]));
                paf[p][3] = ex2h2(h2pack(sa[2*p+1][2], sa[2*p+1][3]));
            }

            const bool ks1_live = (kt * 64 + h * 32 + 16 <= rowmax);

            // --- l += P @ ones ---
            mma_f16(ol, paf[0], ONESH2, ONESH2);
            if (ks1_live) mma_f16(ol, paf[1], ONESH2, ONESH2);

            // --- O += P @ V (keys 32h..32h+31; one ldm4t per dk tile) ---
#pragma unroll
            for (int nt = 0; nt < 8; nt++) {
                uint32_t vb[4];
                ldm4t(vb, vb0 + (uint32_t)nt * 16u + (uint32_t)h * (32u * 144u));
                mma_f16(o[nt], paf[0], vb[0], vb[1]);
                if (ks1_live) mma_f16(o[nt], paf[1], vb[2], vb[3]);
            }
        }
    }
#undef KVSTG

    // ol[0] / ol[2] hold the COMPLETE row sums (mma reduced over k)
    const float inv0 = 1.f / ol[0], inv1 = 1.f / ol[2];

    // Epilogue: g_attnh[b][s][h*64+dk] fp16
    const int b = bh >> 4;
    const int h = bh & 15;
    const int srow0 = qt * 128 + row0 + gg;
#pragma unroll
    for (int nt = 0; nt < 8; nt++) {
        const int dk = nt * 8 + 2 * tt;
        size_t i0 = ((size_t)(b * SS + srow0)) * DD + h * 64 + dk;
        size_t i1 = i0 + (size_t)8 * DD;
        *(uint32_t*)(g_attnh + i0) = h2pack(o[nt][0] * inv0, o[nt][1] * inv0);
        *(uint32_t*)(g_attnh + i1) = h2pack(o[nt][2] * inv1, o[nt][3] * inv1);
    }
}

// ---------------------------------------------------------------------------
extern "C" void kernel_launch(void* const* d_in, const int* in_sizes, int n_in,
                              void* d_out, int out_size)
{
    const float* query = (const float*)d_in[0];
    const float* key_  = (const float*)d_in[1];
    const float* value = (const float*)d_in[2];
    // d_in[3] = mask: causal (tril) -> handled structurally
    const float* W_q = (const float*)d_in[4];
    const float* b_q = (const float*)d_in[5];
    const float* W_k = (const float*)d_in[6];
    const float* b_k = (const float*)d_in[7];
    const float* W_v = (const float*)d_in[8];
    const float* b_v = (const float*)d_in[9];
    const float* W_o = (const float*)d_in[10];
    const float* b_o = (const float*)d_in[11];

    __half *Qh, *Kh, *Vh, *Ah, *xq, *xk, *xv, *wh;
    cudaGetSymbolAddress((void**)&Qh, g_Qh);
    cudaGetSymbolAddress((void**)&Kh, g_Kh);
    cudaGetSymbolAddress((void**)&Vh, g_Vh);
    cudaGetSymbolAddress((void**)&Ah, g_attnh);
    cudaGetSymbolAddress((void**)&xq, g_xq);
    cudaGetSymbolAddress((void**)&xk, g_xk);
    cudaGetSymbolAddress((void**)&xv, g_xv);
    cudaGetSymbolAddress((void**)&wh, g_wh);

    const int NIN = BB * SS * DD;   // 4M
    const int NW  = DD * DD;        // 1M

    cvt_all<<<dim3(256, 1, 7), 256>>>(xq, xk, xv, wh,
                                      query, key_, value,
                                      W_q, W_k, W_v, W_o,
                                      NIN / 4, NW / 4);

    cudaFuncSetAttribute(gemm_qkv,
                         cudaFuncAttributeMaxDynamicSharedMemorySize, GEMM_SMEM);
    cudaFuncSetAttribute(gemm_out,
                         cudaFuncAttributeMaxDynamicSharedMemorySize, GEMM_SMEM);
    cudaFuncSetAttribute(attn_h,
                         cudaFuncAttributeMaxDynamicSharedMemorySize, ATT_SMEM);

    gemm_qkv<<<dim3(4, 32, 3), 512, GEMM_SMEM>>>(xq, xk, xv, wh,
                                                 b_q, b_k, b_v, Qh, Kh, Vh);

    attn_h<<<dim3(SS / 128, BB * HH), 256, ATT_SMEM>>>();

    gemm_out<<<dim3(4, 32), 512, GEMM_SMEM>>>(Ah, wh + (size_t)3 * NW,
                                              b_o, (float*)d_out);
}